// round 4
// baseline (speedup 1.0000x reference)
#include <cuda_runtime.h>
#include <cstdint>

// KNRM: B=128, Q=16, D=1024, E=300, K=11
#define B_SZ 128
#define Q_SZ 16
#define D_SZ 1024
#define E_SZ 300
#define K_SZ 11
#define DC 64                       // doc rows per chunk
#define NCHUNK 16
#define NF4 75                      // real float4 per row (75..80 = zero pad)
#define STR4 81                     // float4 row stride (81 ≡ 1 mod 8)
#define ROWF (STR4 * 4)             // 324 floats
#define DBUF_F4 (DC * STR4)         // 5184
#define DBUF_FLOATS (DBUF_F4 * 4)   // 20736
#define QN_FLOATS (Q_SZ * STR4 * 4) // 5184
#define NT 512

#define SMEM_FLOATS (QN_FLOATS + 2 * DBUF_FLOATS + Q_SZ + Q_SZ * 12)
#define SMEM_BYTES (SMEM_FLOATS * 4)   // 187,456 B

typedef unsigned long long ull;

__device__ __forceinline__ float ex2f(float x) {
    float y;
    asm("ex2.approx.f32 %0, %1;" : "=f"(y) : "f"(x));
    return y;
}

// packed f32x2 FMA: acc += a * b (elementwise on 2 floats)
__device__ __forceinline__ void ffma2(ull& acc, ull a, ull b) {
    asm("fma.rn.f32x2 %0, %1, %2, %0;" : "+l"(acc) : "l"(a), "l"(b));
}

__device__ __forceinline__ float upk(ull v) {
    return __uint_as_float((unsigned)v) + __uint_as_float((unsigned)(v >> 32));
}

__device__ __forceinline__ void cp_async16(uint32_t dst, const float* src) {
    asm volatile("cp.async.cg.shared.global [%0], [%1], 16;" :: "r"(dst), "l"(src));
}
#define CP_COMMIT() asm volatile("cp.async.commit_group;")
#define CP_WAIT1()  asm volatile("cp.async.wait_group 1;")

// full butterfly over the eq lane bits (2,3,4): sums the 8 E-segments
#define RED3(v) { v += __shfl_xor_sync(0xffffffffu, v, 4);  \
                  v += __shfl_xor_sync(0xffffffffu, v, 8);  \
                  v += __shfl_xor_sync(0xffffffffu, v, 16); }

// Gather one 64-row chunk of doc embeddings into smem (async), 512 threads.
__device__ __forceinline__ void prefetch_chunk(const int* __restrict__ toks,
                                               const float* __restrict__ emb,
                                               float* dbuf, int tid)
{
    int d  = tid & 63;
    int fb = tid >> 6;               // 0..7
    long tok = toks[d];
    const float* src = emb + tok * (long)E_SZ;
    uint32_t dst = (uint32_t)__cvta_generic_to_shared(dbuf + d * ROWF);
    for (int f = fb; f < NF4; f += 8)
        cp_async16(dst + (uint32_t)f * 16u, src + f * 4);
}

__global__ void __launch_bounds__(NT, 1)
knrm_kernel(const int* __restrict__ doctoks, const int* __restrict__ querytoks,
            const float* __restrict__ emb, const float* __restrict__ mus,
            const float* __restrict__ sigmas, const float* __restrict__ fcw,
            const float* __restrict__ fcb, float* __restrict__ out)
{
    extern __shared__ float smem[];
    float4* qn4   = (float4*)smem;                 // 16 query rows, stride 81 f4
    float*  dsm   = smem + QN_FLOATS;              // 2 doc-chunk buffers
    float*  rnq_s = dsm + 2 * DBUF_FLOATS;         // 16 inverse query norms
    float*  qfin  = rnq_s + Q_SZ;                  // 16 x 12 final accs
    float*  red   = dsm;                           // end-of-kernel reduction (aliases dsm)

    const int tid = threadIdx.x;
    const int b   = blockIdx.x;
    const int* dtoks_b = doctoks + b * D_SZ;

    // Kick off gather of chunks 0 and 1 immediately.
    prefetch_chunk(dtoks_b, emb, dsm, tid);
    CP_COMMIT();
    prefetch_chunk(dtoks_b + DC, emb, dsm + DBUF_FLOATS, tid);
    CP_COMMIT();

    // Zero the pad float4s (indices 75..80) of every row once.
    {
        float4 z = make_float4(0.f, 0.f, 0.f, 0.f);
        for (int idx = tid; idx < (Q_SZ + 2 * DC) * 6; idx += NT) {
            int r = idx / 6, p = idx - r * 6;
            if (r < Q_SZ) qn4[r * STR4 + NF4 + p] = z;
            else {
                int rr = r - Q_SZ;
                ((float4*)dsm)[(rr >> 6) * DBUF_F4 + (rr & 63) * STR4 + NF4 + p] = z;
            }
        }
    }

    // ---- Phase 1: load 16 query embeddings + inverse norms (1 warp per row) ----
    {
        int q = tid >> 5, p = tid & 31;
        int tok = querytoks[b * Q_SZ + q];
        const float4* src = (const float4*)(emb + (long)tok * E_SZ);
        float4* dst = qn4 + q * STR4;
        float ss = 0.f;
#pragma unroll
        for (int j = 0; j < 3; j++) {
            int f = p + 32 * j;
            if (f < NF4) {
                float4 v = src[f];
                dst[f] = v;
                ss += v.x * v.x + v.y * v.y + v.z * v.z + v.w * v.w;
            }
        }
#pragma unroll
        for (int m = 16; m; m >>= 1) ss += __shfl_xor_sync(0xffffffffu, ss, m);
        if (p == 0) rnq_s[q] = 1.f / (sqrtf(ss) + 1e-9f);
    }
    __syncthreads();

    // Decomposition: tid = dg*32 + eq*4 + qg  (qg: lane bits 0-1, eq: lane bits 2-4)
    const int qg = tid & 3;
    const int eq = (tid >> 2) & 7;
    const int dg = tid >> 5;                       // 0..15
    // segment starts; phase pairs (eq even/odd neighbors) differ by 20 ≡ 4 (mod 8)
    const int off = ((eq & 1) ? 20 : 0) + ((eq & 2) ? 10 : 0) + ((eq & 4) ? 40 : 0);
    const int mh = eq >> 2;                        // d-pair half for RBF
    const int js = eq & 3;                         // q row group for RBF
    const float rq = rnq_s[qg + 4 * js];

    // RBF constants (mu recurrence: 5 regs instead of 22)
    const float mu0   = mus[0];
    const float delta = mus[1] - mus[0];
    float sg = sigmas[0];
    const float c2a = -0.72134752044448169f / (sg * sg);   // exp2 coefficient
    const float mu10 = mus[10];
    sg = sigmas[10];
    const float c2b = -0.72134752044448169f / (sg * sg);

    const int q0i = (qg +  0) * STR4 + off;
    const int q1i = (qg +  4) * STR4 + off;
    const int q2i = (qg +  8) * STR4 + off;
    const int q3i = (qg + 12) * STR4 + off;
    const int d0i = (4 * dg + (qg ^ 0)) * STR4 + off;
    const int d1i = (4 * dg + (qg ^ 1)) * STR4 + off;
    const int d2i = (4 * dg + (qg ^ 2)) * STR4 + off;
    const int d3i = (4 * dg + (qg ^ 3)) * STR4 + off;
    const ulonglong2* qb = (const ulonglong2*)qn4;

    float kq[K_SZ];
#pragma unroll
    for (int k = 0; k < K_SZ; k++) kq[k] = 0.f;
    float simsum = 0.f;

    for (int c = 0; c < NCHUNK; c++) {
        float* dbuf = dsm + (c & 1) * DBUF_FLOATS;
        const ulonglong2* db = (const ulonglong2*)dbuf;
        CP_WAIT1();
        __syncthreads();

        ull a00 = 0, a01 = 0, a02 = 0, a03 = 0;
        ull a10 = 0, a11 = 0, a12 = 0, a13 = 0;
        ull a20 = 0, a21 = 0, a22 = 0, a23 = 0;
        ull a30 = 0, a31 = 0, a32 = 0, a33 = 0;
        ull ssp = 0;

#pragma unroll
        for (int i = 0; i < 10; i++) {
            ulonglong2 Q0 = qb[q0i + i];
            ulonglong2 Q1 = qb[q1i + i];
            ulonglong2 Q2 = qb[q2i + i];
            ulonglong2 Q3 = qb[q3i + i];
            ulonglong2 D0 = db[d0i + i];
            ulonglong2 D1 = db[d1i + i];
            ulonglong2 D2 = db[d2i + i];
            ulonglong2 D3 = db[d3i + i];

            ffma2(ssp, D0.x, D0.x); ffma2(ssp, D0.y, D0.y);

            ffma2(a00, Q0.x, D0.x); ffma2(a00, Q0.y, D0.y);
            ffma2(a01, Q0.x, D1.x); ffma2(a01, Q0.y, D1.y);
            ffma2(a02, Q0.x, D2.x); ffma2(a02, Q0.y, D2.y);
            ffma2(a03, Q0.x, D3.x); ffma2(a03, Q0.y, D3.y);

            ffma2(a10, Q1.x, D0.x); ffma2(a10, Q1.y, D0.y);
            ffma2(a11, Q1.x, D1.x); ffma2(a11, Q1.y, D1.y);
            ffma2(a12, Q1.x, D2.x); ffma2(a12, Q1.y, D2.y);
            ffma2(a13, Q1.x, D3.x); ffma2(a13, Q1.y, D3.y);

            ffma2(a20, Q2.x, D0.x); ffma2(a20, Q2.y, D0.y);
            ffma2(a21, Q2.x, D1.x); ffma2(a21, Q2.y, D1.y);
            ffma2(a22, Q2.x, D2.x); ffma2(a22, Q2.y, D2.y);
            ffma2(a23, Q2.x, D3.x); ffma2(a23, Q2.y, D3.y);

            ffma2(a30, Q3.x, D0.x); ffma2(a30, Q3.y, D0.y);
            ffma2(a31, Q3.x, D1.x); ffma2(a31, Q3.y, D1.y);
            ffma2(a32, Q3.x, D2.x); ffma2(a32, Q3.y, D2.y);
            ffma2(a33, Q3.x, D3.x); ffma2(a33, Q3.y, D3.y);
        }

        // dbuf consumed; start the next gather so cp.async overlaps the tail.
        __syncthreads();
        if (c + 2 < NCHUNK)
            prefetch_chunk(dtoks_b + (c + 2) * DC, emb, dbuf, tid);
        CP_COMMIT();

        // Unpack packed accumulators, then sum the 8 E-segments via shfl.
        float s00 = upk(a00), s01 = upk(a01), s02 = upk(a02), s03 = upk(a03);
        float s10 = upk(a10), s11 = upk(a11), s12 = upk(a12), s13 = upk(a13);
        float s20 = upk(a20), s21 = upk(a21), s22 = upk(a22), s23 = upk(a23);
        float s30 = upk(a30), s31 = upk(a31), s32 = upk(a32), s33 = upk(a33);
        float ssf = upk(ssp);
        RED3(s00); RED3(s01); RED3(s02); RED3(s03);
        RED3(s10); RED3(s11); RED3(s12); RED3(s13);
        RED3(s20); RED3(s21); RED3(s22); RED3(s23);
        RED3(s30); RED3(s31); RED3(s32); RED3(s33);
        RED3(ssf);

        // inverse doc norm of own row (4dg+qg); fetch partner rows over qg bits
        float rn0 = 1.f / (sqrtf(ssf) + 1e-9f);
        float rnA = __shfl_xor_sync(0xffffffffu, rn0, mh ? 2 : 0);
        float rnB = __shfl_xor_sync(0xffffffffu, rn0, mh ? 3 : 1);

        // this thread's two sims: q row qg+4*js, d rows m = {0,1} or {2,3}
        float cA, cB;
        if (js == 0)      { cA = mh ? s02 : s00; cB = mh ? s03 : s01; }
        else if (js == 1) { cA = mh ? s12 : s10; cB = mh ? s13 : s11; }
        else if (js == 2) { cA = mh ? s22 : s20; cB = mh ? s23 : s21; }
        else              { cA = mh ? s32 : s30; cB = mh ? s33 : s31; }

        float sA = cA * rnA * rq;
        float sB = cB * rnB * rq;
        simsum += sA + sB;

        // RBF bank: mu recurrence for the 10 sigma=0.1 channels + special k=10
        float tA = sA - mu0, tB = sB - mu0;
#pragma unroll
        for (int k = 0; k < 10; k++) {
            kq[k] += ex2f(c2a * tA * tA) + ex2f(c2a * tB * tB);
            tA -= delta; tB -= delta;
        }
        tA = sA - mu10; tB = sB - mu10;
        kq[10] += ex2f(c2b * tA * tA) + ex2f(c2b * tB * tB);
    }

    // ---- Final reduction over (dg x eq-half) threads per q ----
    __syncthreads();
    {
        float* r = red + tid * 13;
#pragma unroll
        for (int k = 0; k < K_SZ; k++) r[k] = kq[k];
        r[11] = simsum;
    }
    __syncthreads();
    if (tid < Q_SZ * 12) {
        int q = tid / 12, v = tid - q * 12;
        int jr = q >> 2, qgr = q & 3;
        float sum = 0.f;
        for (int dgi = 0; dgi < 16; dgi++) {
            sum += red[(dgi * 32 + jr * 4 + qgr) * 13 + v];
            sum += red[(dgi * 32 + (jr + 4) * 4 + qgr) * 13 + v];
        }
        qfin[q * 12 + v] = sum;
    }
    __syncthreads();

    // ---- log, mask, Q-sum, FC head ----
    float partial = 0.f;
    if (tid < K_SZ) {
        float acc = 0.f;
        for (int q = 0; q < Q_SZ; q++)
            if (qfin[q * 12 + 11] != 0.0f)
                acc += logf(qfin[q * 12 + tid] + 1e-6f);
        partial = acc * fcw[tid];
    }
    if (tid < 32) {
#pragma unroll
        for (int m = 16; m; m >>= 1)
            partial += __shfl_xor_sync(0xffffffffu, partial, m);
        if (tid == 0) out[b] = partial + fcb[0];
    }
}

extern "C" void kernel_launch(void* const* d_in, const int* in_sizes, int n_in,
                              void* d_out, int out_size)
{
    const int*   doctoks   = (const int*)d_in[0];
    const int*   querytoks = (const int*)d_in[1];
    // d_in[2] = query_idf (unused by the reference)
    const float* emb       = (const float*)d_in[3];
    const float* mus       = (const float*)d_in[4];
    const float* sigmas    = (const float*)d_in[5];
    const float* fc_w      = (const float*)d_in[6];
    const float* fc_b      = (const float*)d_in[7];
    float* out = (float*)d_out;

    cudaFuncSetAttribute(knrm_kernel, cudaFuncAttributeMaxDynamicSharedMemorySize, SMEM_BYTES);
    knrm_kernel<<<B_SZ, NT, SMEM_BYTES>>>(doctoks, querytoks, emb, mus, sigmas,
                                          fc_w, fc_b, out);
}

// round 5
// speedup vs baseline: 1.7436x; 1.7436x over previous
#include <cuda_runtime.h>
#include <cstdint>

// KNRM: B=128, Q=16, D=1024, E=300, K=11
#define B_SZ 128
#define Q_SZ 16
#define D_SZ 1024
#define E_SZ 300
#define K_SZ 11
#define DC 64                       // doc rows per chunk
#define NCHUNK 16
#define NF4 75                      // real float4 per row (75..80 = zero pad)
#define STR4 81                     // float4 row stride (81 == 1 mod 8)
#define ROWF (STR4 * 4)             // 324 floats
#define DBUF_F4 (DC * STR4)         // 5184
#define DBUF_FLOATS (DBUF_F4 * 4)   // 20736
#define QN_FLOATS (Q_SZ * STR4 * 4) // 5184
#define NT 256

#define SMEM_FLOATS (QN_FLOATS + 2 * DBUF_FLOATS + Q_SZ + Q_SZ * 12)
#define SMEM_BYTES (SMEM_FLOATS * 4)   // 187,456 B

typedef unsigned long long ull;

__device__ __forceinline__ float ex2f(float x) {
    float y;
    asm("ex2.approx.f32 %0, %1;" : "=f"(y) : "f"(x));
    return y;
}

// packed f32x2 FMA: acc += a * b (elementwise on 2 floats)
__device__ __forceinline__ void ffma2(ull& acc, ull a, ull b) {
    asm("fma.rn.f32x2 %0, %1, %2, %0;" : "+l"(acc) : "l"(a), "l"(b));
}

__device__ __forceinline__ float upk(ull v) {
    return __uint_as_float((unsigned)v) + __uint_as_float((unsigned)(v >> 32));
}

__device__ __forceinline__ void cp_async16(uint32_t dst, const float* src) {
    asm volatile("cp.async.cg.shared.global [%0], [%1], 16;" :: "r"(dst), "l"(src));
}
#define CP_COMMIT() asm volatile("cp.async.commit_group;")
#define CP_WAIT1()  asm volatile("cp.async.wait_group 1;")
#define CP_WAIT0()  asm volatile("cp.async.wait_group 0;")

#define RED3(v) { v += __shfl_xor_sync(0xffffffffu, v, 4);  \
                  v += __shfl_xor_sync(0xffffffffu, v, 8);  \
                  v += __shfl_xor_sync(0xffffffffu, v, 16); }

// Gather one 64-row chunk of doc embeddings into smem (async), 256 threads.
__device__ __forceinline__ void prefetch_chunk(const int* __restrict__ toks,
                                               const float* __restrict__ emb,
                                               float* dbuf, int tid)
{
    int d  = tid & 63;
    int fb = tid >> 6;               // 0..3
    long tok = toks[d];
    const float* src = emb + tok * (long)E_SZ;
    uint32_t dst = (uint32_t)__cvta_generic_to_shared(dbuf + d * ROWF);
    for (int f = fb; f < NF4; f += 4)
        cp_async16(dst + (uint32_t)f * 16u, src + f * 4);
}

__global__ void __launch_bounds__(NT, 1)
knrm_kernel(const int* __restrict__ doctoks, const int* __restrict__ querytoks,
            const float* __restrict__ emb, const float* __restrict__ mus,
            const float* __restrict__ sigmas, const float* __restrict__ fcw,
            const float* __restrict__ fcb, float* __restrict__ out)
{
    extern __shared__ float smem[];
    float4* qn4   = (float4*)smem;                 // 16 query rows, stride 81 f4
    float*  dsm   = smem + QN_FLOATS;              // 2 doc-chunk buffers
    float*  rnq_s = dsm + 2 * DBUF_FLOATS;         // 16 inverse query norms
    float*  qfin  = rnq_s + Q_SZ;                  // 16 x 12 final accs
    float*  red   = dsm;                           // end-of-kernel reduction (aliases dsm)

    const int tid = threadIdx.x;
    const int b   = blockIdx.x;
    const int* dtoks_b = doctoks + b * D_SZ;

    prefetch_chunk(dtoks_b, emb, dsm, tid);
    CP_COMMIT();
    prefetch_chunk(dtoks_b + DC, emb, dsm + DBUF_FLOATS, tid);
    CP_COMMIT();

    // Zero the pad float4s (indices 75..80) of every row once.
    {
        float4 z = make_float4(0.f, 0.f, 0.f, 0.f);
        for (int idx = tid; idx < (Q_SZ + 2 * DC) * 6; idx += NT) {
            int r = idx / 6, p = idx - r * 6;
            if (r < Q_SZ) qn4[r * STR4 + NF4 + p] = z;
            else {
                int rr = r - Q_SZ;
                ((float4*)dsm)[(rr >> 6) * DBUF_F4 + (rr & 63) * STR4 + NF4 + p] = z;
            }
        }
    }

    // ---- Phase 1: load 16 query embeddings + inverse norms ----
    {
        int q = tid >> 4, p = tid & 15;
        int tok = querytoks[b * Q_SZ + q];
        const float4* src = (const float4*)(emb + (long)tok * E_SZ);
        float4* dst = qn4 + q * STR4;
        float ss = 0.f;
#pragma unroll
        for (int j = 0; j < 5; j++) {
            int f = p + 16 * j;
            if (f < NF4) {
                float4 v = src[f];
                dst[f] = v;
                ss += v.x * v.x + v.y * v.y + v.z * v.z + v.w * v.w;
            }
        }
        ss += __shfl_xor_sync(0xffffffffu, ss, 1);
        ss += __shfl_xor_sync(0xffffffffu, ss, 2);
        ss += __shfl_xor_sync(0xffffffffu, ss, 4);
        ss += __shfl_xor_sync(0xffffffffu, ss, 8);
        if (p == 0) rnq_s[q] = 1.f / (sqrtf(ss) + 1e-9f);
    }
    __syncthreads();

    // tid = dg*32 + eq*4 + qg   (qg: lane b0-1, eq: lane b2-4, dg: 0..7)
    const int lane = tid & 31;
    const int qg = tid & 3;
    const int eq = (tid >> 2) & 7;
    const int dg = tid >> 5;
    const int b0 = eq & 1, b1 = (eq >> 1) & 1, b2 = eq >> 2;
    const int off = (b0 ? 20 : 0) + (b1 ? 10 : 0) + (b2 ? 40 : 0);
    const float rq = rnq_s[qg + 4 * (eq & 3)];

    // RBF constants
    const float mu0   = mus[0];
    const float delta = mus[1] - mus[0];
    float sg = sigmas[0];
    const float c2a = -0.72134752044448169f / (sg * sg);
    const float mu10 = mus[10];
    sg = sigmas[10];
    const float c2b = -0.72134752044448169f / (sg * sg);

    // smem indices (ulonglong2 units == float4 units)
    int qi[4], di[8];
#pragma unroll
    for (int j = 0; j < 4; j++) qi[j] = (qg + 4 * j) * STR4 + off;
#pragma unroll
    for (int m = 0; m < 8; m++) di[m] = (8 * dg + ((qg + m) & 7)) * STR4 + off;
    const ulonglong2* qb = (const ulonglong2*)qn4;

    float kq[K_SZ];
#pragma unroll
    for (int k = 0; k < K_SZ; k++) kq[k] = 0.f;
    float simsum = 0.f;

    for (int c = 0; c < NCHUNK; c++) {
        float* dbuf = dsm + (c & 1) * DBUF_FLOATS;
        const ulonglong2* db = (const ulonglong2*)dbuf;
        CP_WAIT1();
        __syncthreads();

        ull A[4][8];
#pragma unroll
        for (int j = 0; j < 4; j++)
#pragma unroll
            for (int m = 0; m < 8; m++) A[j][m] = 0;
        ull sqA = 0, sqB = 0;

#pragma unroll
        for (int i = 0; i < 10; i++) {
            ulonglong2 Q[4], D[8];
#pragma unroll
            for (int j = 0; j < 4; j++) Q[j] = qb[qi[j] + i];
#pragma unroll
            for (int m = 0; m < 8; m++) D[m] = db[di[m] + i];

            ffma2(sqA, D[0].x, D[0].x); ffma2(sqA, D[0].y, D[0].y);
            ffma2(sqB, D[4].x, D[4].x); ffma2(sqB, D[4].y, D[4].y);

#pragma unroll
            for (int j = 0; j < 4; j++)
#pragma unroll
                for (int m = 0; m < 8; m++) {
                    ffma2(A[j][m], Q[j].x, D[m].x);
                    ffma2(A[j][m], Q[j].y, D[m].y);
                }
        }

        __syncthreads();            // dbuf consumed
        if (c + 2 < NCHUNK)
            prefetch_chunk(dtoks_b + (c + 2) * DC, emb, dbuf, tid);
        CP_COMMIT();                // keep wait_group count aligned

        // --- selection butterfly over eq bits: each thread keeps only what it needs ---
        // Level 1 (xor 4, j bit0): 32 -> 16
        float n1[2][8];
#pragma unroll
        for (int jh = 0; jh < 2; jh++)
#pragma unroll
            for (int m = 0; m < 8; m++) {
                float vA = upk(A[2 * jh][m]);     // j bit0 = 0
                float vB = upk(A[2 * jh + 1][m]); // j bit0 = 1
                float v_send = b0 ? vA : vB;
                float v_keep = b0 ? vB : vA;
                n1[jh][m] = v_keep + __shfl_xor_sync(0xffffffffu, v_send, 4);
            }
        // Level 2 (xor 8, j bit1): 16 -> 8
        float n2[8];
#pragma unroll
        for (int m = 0; m < 8; m++) {
            float v_send = b1 ? n1[0][m] : n1[1][m];
            float v_keep = b1 ? n1[1][m] : n1[0][m];
            n2[m] = v_keep + __shfl_xor_sync(0xffffffffu, v_send, 8);
        }
        // Level 3 (xor 16, m half): 8 -> 4
        float s[4];
#pragma unroll
        for (int t = 0; t < 4; t++) {
            float v_send = b2 ? n2[t] : n2[4 + t];
            float v_keep = b2 ? n2[4 + t] : n2[t];
            s[t] = v_keep + __shfl_xor_sync(0xffffffffu, v_send, 16);
        }

        // doc norms: thread owns rows 8dg+qg (A) and 8dg+qg+4 (B)
        float ssA = upk(sqA), ssB = upk(sqB);
        RED3(ssA); RED3(ssB);
        float rnA = 1.f / (sqrtf(ssA) + 1e-9f);
        float rnB = 1.f / (sqrtf(ssB) + 1e-9f);

        // RBF for 4 sims: q = qg+4*(eq&3), d rows m = 4*b2+t
#pragma unroll
        for (int t = 0; t < 4; t++) {
            int sr = (qg + 4 * b2 + t) & 7;          // row-within-octet
            int src = (lane & 28) | (sr & 3);
            float ra = __shfl_sync(0xffffffffu, rnA, src);
            float rb = __shfl_sync(0xffffffffu, rnB, src);
            float rn = (sr < 4) ? ra : rb;
            float sv = s[t] * rn * rq;
            simsum += sv;
            float tt = sv - mu0;
#pragma unroll
            for (int k = 0; k < 10; k++) {
                kq[k] += ex2f(c2a * tt * tt);
                tt -= delta;
            }
            tt = sv - mu10;
            kq[10] += ex2f(c2b * tt * tt);
        }
    }

    // ---- Final reduction ----
    CP_WAIT0();
    __syncthreads();
    {
        float* r = red + tid * 13;
#pragma unroll
        for (int k = 0; k < K_SZ; k++) r[k] = kq[k];
        r[11] = simsum;
    }
    __syncthreads();
    if (tid < Q_SZ * 12) {
        int q = tid / 12, v = tid - q * 12;
        int jr = q >> 2, qgr = q & 3;
        float sum = 0.f;
        for (int dgi = 0; dgi < 8; dgi++) {
            sum += red[(dgi * 32 + jr * 4 + qgr) * 13 + v];
            sum += red[(dgi * 32 + (jr + 4) * 4 + qgr) * 13 + v];
        }
        qfin[q * 12 + v] = sum;
    }
    __syncthreads();

    // ---- log, mask, Q-sum, FC head ----
    float partial = 0.f;
    if (tid < K_SZ) {
        float acc = 0.f;
        for (int q = 0; q < Q_SZ; q++)
            if (qfin[q * 12 + 11] != 0.0f)
                acc += logf(qfin[q * 12 + tid] + 1e-6f);
        partial = acc * fcw[tid];
    }
    if (tid < 32) {
#pragma unroll
        for (int m = 16; m; m >>= 1)
            partial += __shfl_xor_sync(0xffffffffu, partial, m);
        if (tid == 0) out[b] = partial + fcb[0];
    }
}

extern "C" void kernel_launch(void* const* d_in, const int* in_sizes, int n_in,
                              void* d_out, int out_size)
{
    const int*   doctoks   = (const int*)d_in[0];
    const int*   querytoks = (const int*)d_in[1];
    // d_in[2] = query_idf (unused by the reference)
    const float* emb       = (const float*)d_in[3];
    const float* mus       = (const float*)d_in[4];
    const float* sigmas    = (const float*)d_in[5];
    const float* fc_w      = (const float*)d_in[6];
    const float* fc_b      = (const float*)d_in[7];
    float* out = (float*)d_out;

    cudaFuncSetAttribute(knrm_kernel, cudaFuncAttributeMaxDynamicSharedMemorySize, SMEM_BYTES);
    knrm_kernel<<<B_SZ, NT, SMEM_BYTES>>>(doctoks, querytoks, emb, mus, sigmas,
                                          fc_w, fc_b, out);
}

// round 6
// speedup vs baseline: 1.7504x; 1.0039x over previous
#include <cuda_runtime.h>
#include <cstdint>

// KNRM: B=128, Q=16, D=1024, E=300, K=11. D split across 2 CTAs per batch.
#define B_SZ 128
#define Q_SZ 16
#define D_SZ 1024
#define DHALF 512
#define E_SZ 300
#define K_SZ 11
#define DC 32                       // doc rows per chunk
#define NCHUNK 16                   // 16 * 32 = 512 rows per CTA
#define NF4 75                      // real float4 per row (75..80 = zero pad)
#define STR4 81                     // float4 row stride (81 == 1 mod 8)
#define ROWF (STR4 * 4)             // 324 floats
#define DBUF_F4 (DC * STR4)         // 2592
#define DBUF_FLOATS (DBUF_F4 * 4)   // 10368
#define QN_FLOATS (Q_SZ * STR4 * 4) // 5184
#define NT 256

#define SMEM_FLOATS (QN_FLOATS + 2 * DBUF_FLOATS + Q_SZ)
#define SMEM_BYTES (SMEM_FLOATS * 4)   // 103,744 B -> 2 CTAs/SM

typedef unsigned long long ull;

// per-(batch,half) partials: 16 q x (11 kernels + simsum)
__device__ float g_part[2 * B_SZ * 192];

__device__ __forceinline__ float ex2f(float x) {
    float y;
    asm("ex2.approx.f32 %0, %1;" : "=f"(y) : "f"(x));
    return y;
}

__device__ __forceinline__ void ffma2(ull& acc, ull a, ull b) {
    asm("fma.rn.f32x2 %0, %1, %2, %0;" : "+l"(acc) : "l"(a), "l"(b));
}

__device__ __forceinline__ float upk(ull v) {
    return __uint_as_float((unsigned)v) + __uint_as_float((unsigned)(v >> 32));
}

__device__ __forceinline__ void cp_async16(uint32_t dst, const float* src) {
    asm volatile("cp.async.cg.shared.global [%0], [%1], 16;" :: "r"(dst), "l"(src));
}
#define CP_COMMIT() asm volatile("cp.async.commit_group;")
#define CP_WAIT1()  asm volatile("cp.async.wait_group 1;")
#define CP_WAIT0()  asm volatile("cp.async.wait_group 0;")

#define RED3(v) { v += __shfl_xor_sync(0xffffffffu, v, 4);  \
                  v += __shfl_xor_sync(0xffffffffu, v, 8);  \
                  v += __shfl_xor_sync(0xffffffffu, v, 16); }

// Gather one 32-row chunk of doc embeddings into smem (async), 256 threads.
__device__ __forceinline__ void prefetch_chunk(const int* __restrict__ toks,
                                               const float* __restrict__ emb,
                                               float* dbuf, int tid)
{
    int d  = tid & 31;
    int fb = tid >> 5;               // 0..7
    long tok = toks[d];
    const float* src = emb + tok * (long)E_SZ;
    uint32_t dst = (uint32_t)__cvta_generic_to_shared(dbuf + d * ROWF);
    for (int f = fb; f < NF4; f += 8)
        cp_async16(dst + (uint32_t)f * 16u, src + f * 4);
}

__global__ void __launch_bounds__(NT, 2)
knrm_main(const int* __restrict__ doctoks, const int* __restrict__ querytoks,
          const float* __restrict__ emb, const float* __restrict__ mus,
          const float* __restrict__ sigmas)
{
    extern __shared__ float smem[];
    float4* qn4   = (float4*)smem;                 // 16 query rows, stride 81 f4
    float*  dsm   = smem + QN_FLOATS;              // 2 doc-chunk buffers
    float*  rnq_s = dsm + 2 * DBUF_FLOATS;         // 16 inverse query norms
    float*  red   = dsm;                           // end-of-kernel reduction (aliases dsm)

    const int tid = threadIdx.x;
    const int bid = blockIdx.x;
    const int b   = bid >> 1;
    const int h   = bid & 1;
    const int* dtoks_b = doctoks + b * D_SZ + h * DHALF;

    prefetch_chunk(dtoks_b, emb, dsm, tid);
    CP_COMMIT();
    prefetch_chunk(dtoks_b + DC, emb, dsm + DBUF_FLOATS, tid);
    CP_COMMIT();

    // Zero the pad float4s (indices 75..80) of every row once.
    {
        float4 z = make_float4(0.f, 0.f, 0.f, 0.f);
        for (int idx = tid; idx < (Q_SZ + 2 * DC) * 6; idx += NT) {
            int r = idx / 6, p = idx - r * 6;
            if (r < Q_SZ) qn4[r * STR4 + NF4 + p] = z;
            else {
                int rr = r - Q_SZ;
                ((float4*)dsm)[(rr >> 5) * DBUF_F4 + (rr & 31) * STR4 + NF4 + p] = z;
            }
        }
    }

    // ---- load 16 query embeddings + inverse norms ----
    {
        int q = tid >> 4, p = tid & 15;
        int tok = querytoks[b * Q_SZ + q];
        const float4* src = (const float4*)(emb + (long)tok * E_SZ);
        float4* dst = qn4 + q * STR4;
        float ss = 0.f;
#pragma unroll
        for (int j = 0; j < 5; j++) {
            int f = p + 16 * j;
            if (f < NF4) {
                float4 v = src[f];
                dst[f] = v;
                ss += v.x * v.x + v.y * v.y + v.z * v.z + v.w * v.w;
            }
        }
        ss += __shfl_xor_sync(0xffffffffu, ss, 1);
        ss += __shfl_xor_sync(0xffffffffu, ss, 2);
        ss += __shfl_xor_sync(0xffffffffu, ss, 4);
        ss += __shfl_xor_sync(0xffffffffu, ss, 8);
        if (p == 0) rnq_s[q] = 1.f / (sqrtf(ss) + 1e-9f);
    }
    __syncthreads();

    // tid = dg*32 + eq*4 + qg  (warp = dg, lane = eq*4+qg)
    const int lane = tid & 31;
    const int qg = tid & 3;
    const int eq = (tid >> 2) & 7;
    const int dg = tid >> 5;                       // 0..7, owns rows 4dg..4dg+3
    const int b0 = eq & 1, b1 = (eq >> 1) & 1, b2 = eq >> 2;
    const int off = (b0 ? 20 : 0) + (b1 ? 10 : 0) + (b2 ? 40 : 0);
    const float rq = rnq_s[qg + 4 * (eq & 3)];

    // RBF constants
    const float mu0   = mus[0];
    const float delta = mus[1] - mus[0];
    float sg = sigmas[0];
    const float c2a = -0.72134752044448169f / (sg * sg);
    const float mu10 = mus[10];
    sg = sigmas[10];
    const float c2b = -0.72134752044448169f / (sg * sg);

    int qi[4], di[4];
#pragma unroll
    for (int j = 0; j < 4; j++) qi[j] = (qg + 4 * j) * STR4 + off;
#pragma unroll
    for (int m = 0; m < 4; m++) di[m] = (4 * dg + ((qg + m) & 3)) * STR4 + off;
    const ulonglong2* qb = (const ulonglong2*)qn4;

    float kq[K_SZ];
#pragma unroll
    for (int k = 0; k < K_SZ; k++) kq[k] = 0.f;
    float simsum = 0.f;

    for (int c = 0; c < NCHUNK; c++) {
        float* dbuf = dsm + (c & 1) * DBUF_FLOATS;
        const ulonglong2* db = (const ulonglong2*)dbuf;
        CP_WAIT1();
        __syncthreads();

        ull A[4][4];
#pragma unroll
        for (int j = 0; j < 4; j++)
#pragma unroll
            for (int m = 0; m < 4; m++) A[j][m] = 0;
        ull ssp = 0;

#pragma unroll
        for (int i = 0; i < 10; i++) {
            ulonglong2 Q[4], D[4];
#pragma unroll
            for (int j = 0; j < 4; j++) Q[j] = qb[qi[j] + i];
#pragma unroll
            for (int m = 0; m < 4; m++) D[m] = db[di[m] + i];

            ffma2(ssp, D[0].x, D[0].x); ffma2(ssp, D[0].y, D[0].y);

#pragma unroll
            for (int j = 0; j < 4; j++)
#pragma unroll
                for (int m = 0; m < 4; m++) {
                    ffma2(A[j][m], Q[j].x, D[m].x);
                    ffma2(A[j][m], Q[j].y, D[m].y);
                }
        }

        __syncthreads();            // dbuf consumed
        if (c + 2 < NCHUNK)
            prefetch_chunk(dtoks_b + (c + 2) * DC, emb, dbuf, tid);
        CP_COMMIT();                // keep wait_group count aligned

        // --- selection butterfly over eq bits: 16 accs -> 2 sims/thread ---
        // L1 (xor 4, j bit0): keep j with bit0 == b0
        float n1[2][4];
#pragma unroll
        for (int jh = 0; jh < 2; jh++)
#pragma unroll
            for (int m = 0; m < 4; m++) {
                float vA = upk(A[2 * jh][m]);     // j bit0 = 0
                float vB = upk(A[2 * jh + 1][m]); // j bit0 = 1
                float v_send = b0 ? vA : vB;
                float v_keep = b0 ? vB : vA;
                n1[jh][m] = v_keep + __shfl_xor_sync(0xffffffffu, v_send, 4);
            }
        // L2 (xor 8, j bit1): keep j bit1 == b1
        float n2[4];
#pragma unroll
        for (int m = 0; m < 4; m++) {
            float v_send = b1 ? n1[0][m] : n1[1][m];
            float v_keep = b1 ? n1[1][m] : n1[0][m];
            n2[m] = v_keep + __shfl_xor_sync(0xffffffffu, v_send, 8);
        }
        // L3 (xor 16, m pair): keep m in {2*b2, 2*b2+1}
        float s[2];
#pragma unroll
        for (int t = 0; t < 2; t++) {
            float v_send = b2 ? n2[t] : n2[2 + t];
            float v_keep = b2 ? n2[2 + t] : n2[t];
            s[t] = v_keep + __shfl_xor_sync(0xffffffffu, v_send, 16);
        }

        // doc norm of own row 4dg+qg (full E after RED3)
        float ssf = upk(ssp);
        RED3(ssf);
        float rn0 = 1.f / (sqrtf(ssf) + 1e-9f);

        // RBF for 2 sims: q = qg+4*(eq&3), d row = 4dg + ((qg+2*b2+t)&3)
#pragma unroll
        for (int t = 0; t < 2; t++) {
            int qgp = (qg + 2 * b2 + t) & 3;
            float rn = __shfl_sync(0xffffffffu, rn0, (lane & 28) | qgp);
            float sv = s[t] * rn * rq;
            simsum += sv;
            float tt = sv - mu0;
#pragma unroll
            for (int k = 0; k < 10; k++) {
                kq[k] += ex2f(c2a * tt * tt);
                tt -= delta;
            }
            tt = sv - mu10;
            kq[10] += ex2f(c2b * tt * tt);
        }
    }

    // ---- reduce over (dg x b2) threads per q, write partials to global ----
    CP_WAIT0();
    __syncthreads();
    {
        float* r = red + tid * 13;
#pragma unroll
        for (int k = 0; k < K_SZ; k++) r[k] = kq[k];
        r[11] = simsum;
    }
    __syncthreads();
    if (tid < Q_SZ * 12) {
        int q = tid / 12, v = tid - q * 12;
        int jr = q >> 2, qgr = q & 3;
        float sum = 0.f;
#pragma unroll
        for (int dgi = 0; dgi < 8; dgi++) {
            sum += red[(dgi * 32 + jr * 4 + qgr) * 13 + v];
            sum += red[(dgi * 32 + 16 + jr * 4 + qgr) * 13 + v];
        }
        g_part[bid * 192 + tid] = sum;
    }
}

// Combine the two D-halves, apply mask/log, Q-sum, FC head.
__global__ void knrm_final(const float* __restrict__ fcw,
                           const float* __restrict__ fcb,
                           float* __restrict__ out)
{
    __shared__ float qf[192];
    const int b = blockIdx.x;
    const int tid = threadIdx.x;
    if (tid < 192)
        qf[tid] = g_part[(2 * b) * 192 + tid] + g_part[(2 * b + 1) * 192 + tid];
    __syncthreads();

    float partial = 0.f;
    if (tid < K_SZ) {
        float acc = 0.f;
        for (int q = 0; q < Q_SZ; q++)
            if (qf[q * 12 + 11] != 0.0f)
                acc += logf(qf[q * 12 + tid] + 1e-6f);
        partial = acc * fcw[tid];
    }
    if (tid < 32) {
#pragma unroll
        for (int m = 16; m; m >>= 1)
            partial += __shfl_xor_sync(0xffffffffu, partial, m);
        if (tid == 0) out[b] = partial + fcb[0];
    }
}

extern "C" void kernel_launch(void* const* d_in, const int* in_sizes, int n_in,
                              void* d_out, int out_size)
{
    const int*   doctoks   = (const int*)d_in[0];
    const int*   querytoks = (const int*)d_in[1];
    // d_in[2] = query_idf (unused by the reference)
    const float* emb       = (const float*)d_in[3];
    const float* mus       = (const float*)d_in[4];
    const float* sigmas    = (const float*)d_in[5];
    const float* fc_w      = (const float*)d_in[6];
    const float* fc_b      = (const float*)d_in[7];
    float* out = (float*)d_out;

    cudaFuncSetAttribute(knrm_main, cudaFuncAttributeMaxDynamicSharedMemorySize, SMEM_BYTES);
    knrm_main<<<2 * B_SZ, NT, SMEM_BYTES>>>(doctoks, querytoks, emb, mus, sigmas);
    knrm_final<<<B_SZ, 192>>>(fc_w, fc_b, out);
}

// round 9
// speedup vs baseline: 2.6895x; 1.5365x over previous
#include <cuda_runtime.h>
#include <cstdint>

// KNRM via warp-level bf16 mma.sync (3-split): B=128, Q=16, D=1024, E=300, K=11
#define B_SZ 128
#define Q_SZ 16
#define D_SZ 1024
#define E_SZ 300
#define K_SZ 11
#define MT 128                   // doc rows per tile
#define NTILE 8
#define NKS 19                   // k-steps of 16 (covers 304 >= 300)
#define STRB 624                 // row stride bytes (312 bf16 cols; 624 = 39*16 -> conflict-free)

// smem byte offsets
#define OFF_AHI  0
#define OFF_ALO  (OFF_AHI + 128 * STRB)     // 79872
#define OFF_BHI  (OFF_ALO + 128 * STRB)     // 159744
#define OFF_BLO  (OFF_BHI + 16 * STRB)      // 169728
#define OFF_RND  (OFF_BLO + 16 * STRB)      // 179712 : 128 floats
#define OFF_RNQ  (OFF_RND + 512)            // 180224 : 16 floats
#define OFF_QFIN (OFF_RNQ + 64)             // 180288 : 192 floats
#define SMEM_BYTES (OFF_QFIN + 768 + 16)    // 181072

__device__ __forceinline__ uint32_t smem_u32(const void* p) {
    uint32_t a;
    asm("{ .reg .u64 t; cvta.to.shared.u64 t, %1; cvt.u32.u64 %0, t; }" : "=r"(a) : "l"(p));
    return a;
}
__device__ __forceinline__ float ex2f(float x) {
    float y; asm("ex2.approx.f32 %0, %1;" : "=f"(y) : "f"(x)); return y;
}
__device__ __forceinline__ uint32_t packbf(float lo, float hi) {
    uint32_t r;
    asm("cvt.rn.bf16x2.f32 %0, %1, %2;" : "=r"(r) : "f"(hi), "f"(lo));
    return r;
}
__device__ __forceinline__ void sts64(uint32_t a, uint32_t x, uint32_t y) {
    asm volatile("st.shared.v2.b32 [%0], {%1, %2};" :: "r"(a), "r"(x), "r"(y) : "memory");
}
__device__ __forceinline__ void ldsm4(uint32_t& r0, uint32_t& r1, uint32_t& r2, uint32_t& r3,
                                      uint32_t addr) {
    asm volatile("ldmatrix.sync.aligned.m8n8.x4.shared.b16 {%0,%1,%2,%3}, [%4];"
                 : "=r"(r0), "=r"(r1), "=r"(r2), "=r"(r3) : "r"(addr));
}
__device__ __forceinline__ void mma_bf16(float* c, uint32_t a0, uint32_t a1, uint32_t a2,
                                         uint32_t a3, uint32_t b0, uint32_t b1) {
    asm volatile(
        "mma.sync.aligned.m16n8k16.row.col.f32.bf16.bf16.f32 "
        "{%0,%1,%2,%3}, {%4,%5,%6,%7}, {%8,%9}, {%0,%1,%2,%3};"
        : "+f"(c[0]), "+f"(c[1]), "+f"(c[2]), "+f"(c[3])
        : "r"(a0), "r"(a1), "r"(a2), "r"(a3), "r"(b0), "r"(b1));
}

#define REDW(v) { v += __shfl_xor_sync(0xffffffffu, v, 4);  \
                  v += __shfl_xor_sync(0xffffffffu, v, 8);  \
                  v += __shfl_xor_sync(0xffffffffu, v, 16); }

// Convert one float4 (cols 4f..4f+3 of row r) to bf16 hi/lo and store (row-major).
__device__ __forceinline__ void conv_store(float4 v, uint32_t hi_base, uint32_t lo_base,
                                           int r, int f, float& ssq) {
    ssq += v.x * v.x + v.y * v.y + v.z * v.z + v.w * v.w;
    uint32_t h0 = packbf(v.x, v.y);
    uint32_t h1 = packbf(v.z, v.w);
    float fx = __uint_as_float(h0 << 16), fy = __uint_as_float(h0 & 0xffff0000u);
    float fz = __uint_as_float(h1 << 16), fw = __uint_as_float(h1 & 0xffff0000u);
    uint32_t l0 = packbf(v.x - fx, v.y - fy);
    uint32_t l1 = packbf(v.z - fz, v.w - fw);
    uint32_t o = (uint32_t)r * STRB + (uint32_t)f * 8u;
    sts64(hi_base + o, h0, h1);
    sts64(lo_base + o, l0, l1);
}

__global__ void __launch_bounds__(256, 1)
knrm_mma(const int* __restrict__ doctoks, const int* __restrict__ querytoks,
         const float* __restrict__ emb, const float* __restrict__ mus,
         const float* __restrict__ sigmas, const float* __restrict__ fcw,
         const float* __restrict__ fcb, float* __restrict__ out)
{
    extern __shared__ char smb[];
    const uint32_t sb = smem_u32(smb);
    float* rnd  = (float*)(smb + OFF_RND);
    float* rnq  = (float*)(smb + OFF_RNQ);
    float* qfin = (float*)(smb + OFF_QFIN);

    const int tid = threadIdx.x;
    const int b   = blockIdx.x;
    const int wid = tid >> 5, lane = tid & 31;

    // Zero padding cols 300..311 (24 B at byte offset 600) of all 288 rows.
    if (tid < 288) {
        uint32_t base;
        if (tid < 128)      base = sb + OFF_AHI + tid * STRB;
        else if (tid < 256) base = sb + OFF_ALO + (tid - 128) * STRB;
        else if (tid < 272) base = sb + OFF_BHI + (tid - 256) * STRB;
        else                base = sb + OFF_BLO + (tid - 272) * STRB;
        sts64(base + 600, 0u, 0u);
        sts64(base + 608, 0u, 0u);
        sts64(base + 616, 0u, 0u);
    }

    // ---- Query tile: convert to bf16 hi/lo + inverse norms ----
    {
        int q = tid >> 4, p = tid & 15;
        int tok = querytoks[b * Q_SZ + q];
        const float4* src = (const float4*)(emb + (long)tok * E_SZ);
        float ss = 0.f;
#pragma unroll
        for (int i = 0; i < 5; i++) {
            int f = p + 16 * i;
            if (f < 75)
                conv_store(src[f], sb + OFF_BHI, sb + OFF_BLO, q, f, ss);
        }
        ss += __shfl_xor_sync(0xffffffffu, ss, 1);
        ss += __shfl_xor_sync(0xffffffffu, ss, 2);
        ss += __shfl_xor_sync(0xffffffffu, ss, 4);
        ss += __shfl_xor_sync(0xffffffffu, ss, 8);
        if (p == 0) rnq[q] = 1.f / (sqrtf(ss) + 1e-9f);
    }
    __syncthreads();

    // RBF constants
    const float mu0   = mus[0];
    const float delta = mus[1] - mus[0];
    float sg = sigmas[0];
    const float c2a = -0.72134752044448169f / (sg * sg);
    const float mu10 = mus[10];
    sg = sigmas[10];
    const float c2b = -0.72134752044448169f / (sg * sg);

    // ldmatrix lane addressing: row = lane&15, k offset = 8*(lane>>4)
    const uint32_t lrow = lane & 15;
    const uint32_t lkof = (uint32_t)(lane >> 4) * 16u;   // 8 cols * 2 B
    const uint32_t aAH = sb + OFF_AHI + (16 * wid + lrow) * STRB + lkof;
    const uint32_t aAL = sb + OFF_ALO + (16 * wid + lrow) * STRB + lkof;
    const uint32_t aBH = sb + OFF_BHI + lrow * STRB + lkof;
    const uint32_t aBL = sb + OFF_BLO + lrow * STRB + lkof;

    // this thread's sim coordinates
    const int m  = lane & 3;
    const int r0 = 16 * wid + (lane >> 2);   // row within tile
    const int r1 = r0 + 8;
    float rq[4];
#pragma unroll
    for (int j = 0; j < 4; j++)
        rq[j] = rnq[2 * m + (j & 1) + 8 * (j >> 1)];

    float kq[4][K_SZ], ssim[4];
#pragma unroll
    for (int j = 0; j < 4; j++) {
        ssim[j] = 0.f;
#pragma unroll
        for (int k = 0; k < K_SZ; k++) kq[j][k] = 0.f;
    }

    for (int c = 0; c < NTILE; c++) {
        // ---- gather + convert 128 doc rows (2 threads per row) ----
        {
            int rt = tid >> 1, p = tid & 1;
            int tok = doctoks[b * D_SZ + c * MT + rt];
            const float4* src = (const float4*)(emb + (long)tok * E_SZ);
            float ss = 0.f;
#pragma unroll
            for (int i = 0; i < 38; i++) {
                int f = p + 2 * i;
                if (f < 75)
                    conv_store(src[f], sb + OFF_AHI, sb + OFF_ALO, rt, f, ss);
            }
            ss += __shfl_xor_sync(0xffffffffu, ss, 1);
            if (p == 0) rnd[rt] = 1.f / (sqrtf(ss) + 1e-9f);
        }
        __syncthreads();

        // ---- MMA: 19 k-steps, 3 split-passes fused per step ----
        float acc[8];
#pragma unroll
        for (int i = 0; i < 8; i++) acc[i] = 0.f;

#pragma unroll
        for (int ks = 0; ks < NKS; ks++) {
            uint32_t ko = (uint32_t)ks * 32u;   // 16 cols * 2 B
            uint32_t ah0, ah1, ah2, ah3, al0, al1, al2, al3;
            uint32_t bh0, bh1, bh2, bh3, bl0, bl1, bl2, bl3;
            ldsm4(ah0, ah1, ah2, ah3, aAH + ko);
            ldsm4(al0, al1, al2, al3, aAL + ko);
            ldsm4(bh0, bh1, bh2, bh3, aBH + ko);
            ldsm4(bl0, bl1, bl2, bl3, aBL + ko);
            // hi*hi
            mma_bf16(acc,     ah0, ah1, ah2, ah3, bh0, bh2);
            mma_bf16(acc + 4, ah0, ah1, ah2, ah3, bh1, bh3);
            // hi*lo
            mma_bf16(acc,     ah0, ah1, ah2, ah3, bl0, bl2);
            mma_bf16(acc + 4, ah0, ah1, ah2, ah3, bl1, bl3);
            // lo*hi
            mma_bf16(acc,     al0, al1, al2, al3, bh0, bh2);
            mma_bf16(acc + 4, al0, al1, al2, al3, bh1, bh3);
        }

        // ---- normalize + RBF (sims live in registers) ----
        float rd0 = rnd[r0], rd1 = rnd[r1];
        float sv[8];
        sv[0] = acc[0] * rd0 * rq[0];
        sv[1] = acc[1] * rd0 * rq[1];
        sv[2] = acc[2] * rd1 * rq[0];
        sv[3] = acc[3] * rd1 * rq[1];
        sv[4] = acc[4] * rd0 * rq[2];
        sv[5] = acc[5] * rd0 * rq[3];
        sv[6] = acc[6] * rd1 * rq[2];
        sv[7] = acc[7] * rd1 * rq[3];
        const int jmap[8] = {0, 1, 0, 1, 2, 3, 2, 3};
#pragma unroll
        for (int i = 0; i < 8; i++) {
            int j = jmap[i];
            float s = sv[i];
            ssim[j] += s;
            float tt = s - mu0;
#pragma unroll
            for (int k = 0; k < 10; k++) {
                kq[j][k] += ex2f(c2a * tt * tt);
                tt -= delta;
            }
            tt = s - mu10;
            kq[j][10] += ex2f(c2b * tt * tt);
        }
        __syncthreads();    // before next tile overwrites A / rnd
    }

    // ---- reduce within warp over lane bits 2,3,4 (rows), then across warps ----
#pragma unroll
    for (int j = 0; j < 4; j++) {
        REDW(ssim[j]);
#pragma unroll
        for (int k = 0; k < K_SZ; k++) REDW(kq[j][k]);
    }
    float* red = (float*)(smb + OFF_AHI);   // reuse A buffer: 8 warps x 16 q x 12
    if (lane < 4) {
#pragma unroll
        for (int j = 0; j < 4; j++) {
            int q = 2 * lane + (j & 1) + 8 * (j >> 1);
            float* r = red + (wid * 16 + q) * 12;
#pragma unroll
            for (int k = 0; k < K_SZ; k++) r[k] = kq[j][k];
            r[11] = ssim[j];
        }
    }
    __syncthreads();
    if (tid < Q_SZ * 12) {
        int q = tid / 12, v = tid - q * 12;
        float sum = 0.f;
#pragma unroll
        for (int w = 0; w < 8; w++)
            sum += red[(w * 16 + q) * 12 + v];
        qfin[q * 12 + v] = sum;
    }
    __syncthreads();

    // ---- log, mask, Q-sum, FC head ----
    float partial = 0.f;
    if (tid < K_SZ) {
        float acc2 = 0.f;
        for (int q = 0; q < Q_SZ; q++)
            if (qfin[q * 12 + 11] != 0.0f)
                acc2 += logf(qfin[q * 12 + tid] + 1e-6f);
        partial = acc2 * fcw[tid];
    }
    if (tid < 32) {
#pragma unroll
        for (int mm = 16; mm; mm >>= 1)
            partial += __shfl_xor_sync(0xffffffffu, partial, mm);
        if (tid == 0) out[b] = partial + fcb[0];
    }
}

extern "C" void kernel_launch(void* const* d_in, const int* in_sizes, int n_in,
                              void* d_out, int out_size)
{
    const int*   doctoks   = (const int*)d_in[0];
    const int*   querytoks = (const int*)d_in[1];
    // d_in[2] = query_idf (unused by the reference)
    const float* emb       = (const float*)d_in[3];
    const float* mus       = (const float*)d_in[4];
    const float* sigmas    = (const float*)d_in[5];
    const float* fc_w      = (const float*)d_in[6];
    const float* fc_b      = (const float*)d_in[7];
    float* out = (float*)d_out;

    cudaFuncSetAttribute(knrm_mma, cudaFuncAttributeMaxDynamicSharedMemorySize, SMEM_BYTES);
    knrm_mma<<<B_SZ, 256, SMEM_BYTES>>>(doctoks, querytoks, emb, mus, sigmas,
                                        fc_w, fc_b, out);
}